// round 13
// baseline (speedup 1.0000x reference)
#include <cuda_runtime.h>

// SSN superpixel EM, sparse 9-neighborhood formulation.
// B=4, H=W=256, C=20, 16x16 superpixel grid, cell=16x16, K=256, 10 EM iters.

#define BN     4
#define HH     256
#define NN     (HH*HH)      // 65536 pixels
#define CC     20
#define KGRID  16
#define KK     (KGRID*KGRID)
#define CELLSZ 16
#define PS     258          // even smem stride: float2-aligned rows, conflict-free stride-1 access
#define NWORK  (BN * KK)    // 1024 (b, cell) work items
#define EMGRID 512          // single-wave grid: each block does 2 work items

// Scratch (device globals: no allocation allowed)
__device__ float g_mean[BN * KK * CC];
__device__ float g_partA[BN * KK * 9 * 21];
__device__ float g_partB[BN * KK * 9 * 21];

// ---------------------------------------------------------------------------
// INIT: mean of features within each initial 16x16 cell. grid=(K,B), 256 thr.
// ---------------------------------------------------------------------------
__global__ __launch_bounds__(256) void ssn_init_mean(const float* __restrict__ feat) {
    const int b = blockIdx.y, cell = blockIdx.x, t = threadIdx.x;
    const int py = cell >> 4, px = cell & 15;
    const int r = t >> 4, cc = t & 15;
    const int n = (py * CELLSZ + r) * HH + px * CELLSZ + cc;

    const float4* fp = reinterpret_cast<const float4*>(feat + (size_t)(b * NN + n) * CC);
    float f[CC];
    {
        float4 v;
        v = fp[0]; f[0]=v.x; f[1]=v.y; f[2]=v.z; f[3]=v.w;
        v = fp[1]; f[4]=v.x; f[5]=v.y; f[6]=v.z; f[7]=v.w;
        v = fp[2]; f[8]=v.x; f[9]=v.y; f[10]=v.z; f[11]=v.w;
        v = fp[3]; f[12]=v.x; f[13]=v.y; f[14]=v.z; f[15]=v.w;
        v = fp[4]; f[16]=v.x; f[17]=v.y; f[18]=v.z; f[19]=v.w;
    }

    __shared__ float ssum[CC];
    if (t < CC) ssum[t] = 0.0f;
    __syncthreads();

    const int lane = t & 31;
    #pragma unroll
    for (int c = 0; c < CC; ++c) {
        float v = f[c];
        #pragma unroll
        for (int off = 16; off > 0; off >>= 1)
            v += __shfl_xor_sync(0xffffffffu, v, off);
        if (lane == 0) atomicAdd(&ssum[c], v);
    }
    __syncthreads();
    if (t < CC) g_mean[(b * KK + cell) * CC + t] = ssum[t] * (1.0f / 256.0f);
}

// ---------------------------------------------------------------------------
// EM iteration (fused mean-finalize + E-step + tiled M-step, float2-paired).
// Single-wave grid: EMGRID blocks; block handles work w = bid and w + EMGRID.
// w -> b = w >> 8, cell = w & 255 (so both works share the same cell).
// mode: 0 = read g_mean, write g_partA
//       1 = read g_partA, write g_partB
//       2 = read g_partB, write g_partA
// ---------------------------------------------------------------------------
__global__ __launch_bounds__(256, 5) void ssn_em_iter(const float* __restrict__ feat, int mode) {
    __shared__ __align__(16) float p_s[9 * PS];         // p_s[j][pix]
    __shared__ __align__(16) float f_s[CC * PS];        // f_s[c][pix]
    __shared__ __align__(16) float mean_s[9 * CC];      // float4-read (rows 80B)
    __shared__ float msq_s[9];
    __shared__ float raw_s[9 * 21 + 3];

    const int t = threadIdx.x;
    const int cell = blockIdx.x & 255;                  // same cell for both works
    const int py = cell >> 4, px = cell & 15;

    // geometry shared by both works (cell-dependent only)
    const int r = t >> 4, cc2 = t & 15;
    const int npix = (py * CELLSZ + r) * HH + px * CELLSZ + cc2;

    #pragma unroll 1
    for (int half = 0; half < 2; ++half) {
        const int w = blockIdx.x + half * EMGRID;
        const int b = w >> 8;

        __syncthreads();   // protect smem reuse across the two passes

        // -------- prologue: assemble the 9 neighbor-superpixel means --------
        if (mode == 0) {
            if (t < 9 * CC) {
                const int j = t / CC, c = t % CC;
                const int ky = py + j / 3 - 1, kx = px + j % 3 - 1;
                float m = 0.0f;
                if (ky >= 0 && ky < KGRID && kx >= 0 && kx < KGRID)
                    m = g_mean[(b * KK + ky * KGRID + kx) * CC + c];
                mean_s[t] = m;
            }
        } else {
            const float* __restrict__ src = (mode == 1) ? g_partA : g_partB;
            if (t < 9 * 21) {
                const int j = t / 21, c = t % 21;
                const int ky = py + j / 3 - 1, kx = px + j % 3 - 1;
                float s = 0.0f;
                if (ky >= 0 && ky < KGRID && kx >= 0 && kx < KGRID) {
                    #pragma unroll
                    for (int dy = -1; dy <= 1; ++dy)
                        #pragma unroll
                        for (int dx = -1; dx <= 1; ++dx) {
                            const int cy = ky + dy, cx = kx + dx;
                            if (cy >= 0 && cy < KGRID && cx >= 0 && cx < KGRID) {
                                const int jj = (ky - cy + 1) * 3 + (kx - cx + 1);
                                s += src[((b * KK + cy * KGRID + cx) * 9 + jj) * 21 + c];
                            }
                        }
                }
                raw_s[t] = s;
            }
            __syncthreads();
            if (t < 9 * CC) {
                const int j = t / CC, c = t % CC;
                mean_s[t] = raw_s[j * 21 + c] / fmaxf(raw_s[j * 21 + 20], 1e-12f);
            }
        }
        __syncthreads();
        if (t < 9) {
            float s = 0.0f;
            #pragma unroll
            for (int c = 0; c < CC; ++c) { const float m = mean_s[t * CC + c]; s += m * m; }
            msq_s[t] = s;
        }
        __syncthreads();

        // -------- E-step: one pixel per thread --------
        // softmax(-dist) invariant to ||f||^2: p[j] ∝ exp(2*dot_j - msq_j).
        const float4* fp = reinterpret_cast<const float4*>(feat + (size_t)(b * NN + npix) * CC);
        float4 fv0 = fp[0], fv1 = fp[1], fv2 = fp[2], fv3 = fp[3], fv4 = fp[4];

        float s[9];
        float smax = -1e30f;
        #pragma unroll
        for (int j = 0; j < 9; ++j) {
            const int ky = py + j / 3 - 1, kx = px + j % 3 - 1;
            if (ky >= 0 && ky < KGRID && kx >= 0 && kx < KGRID) {
                const float4* mr = reinterpret_cast<const float4*>(mean_s + j * CC);
                float dot = 0.0f;
                float4 m;
                m = mr[0]; dot = fmaf(fv0.x,m.x,fmaf(fv0.y,m.y,fmaf(fv0.z,m.z,fmaf(fv0.w,m.w,dot))));
                m = mr[1]; dot = fmaf(fv1.x,m.x,fmaf(fv1.y,m.y,fmaf(fv1.z,m.z,fmaf(fv1.w,m.w,dot))));
                m = mr[2]; dot = fmaf(fv2.x,m.x,fmaf(fv2.y,m.y,fmaf(fv2.z,m.z,fmaf(fv2.w,m.w,dot))));
                m = mr[3]; dot = fmaf(fv3.x,m.x,fmaf(fv3.y,m.y,fmaf(fv3.z,m.z,fmaf(fv3.w,m.w,dot))));
                m = mr[4]; dot = fmaf(fv4.x,m.x,fmaf(fv4.y,m.y,fmaf(fv4.z,m.z,fmaf(fv4.w,m.w,dot))));
                s[j] = 2.0f * dot - msq_s[j];
                smax = fmaxf(smax, s[j]);
            } else {
                s[j] = -1e30f;
            }
        }
        float p[9], denom = 0.0f;
        #pragma unroll
        for (int j = 0; j < 9; ++j) {
            p[j] = (s[j] > -1e29f) ? __expf(s[j] - smax) : 0.0f;
            denom += p[j];
        }
        const float inv = 1.0f / denom;   // denom >= 1 (argmax contributes exp(0)=1)
        #pragma unroll
        for (int j = 0; j < 9; ++j) p_s[j * PS + t] = p[j] * inv;
        f_s[ 0 * PS + t] = fv0.x; f_s[ 1 * PS + t] = fv0.y; f_s[ 2 * PS + t] = fv0.z; f_s[ 3 * PS + t] = fv0.w;
        f_s[ 4 * PS + t] = fv1.x; f_s[ 5 * PS + t] = fv1.y; f_s[ 6 * PS + t] = fv1.z; f_s[ 7 * PS + t] = fv1.w;
        f_s[ 8 * PS + t] = fv2.x; f_s[ 9 * PS + t] = fv2.y; f_s[10 * PS + t] = fv2.z; f_s[11 * PS + t] = fv2.w;
        f_s[12 * PS + t] = fv3.x; f_s[13 * PS + t] = fv3.y; f_s[14 * PS + t] = fv3.z; f_s[15 * PS + t] = fv3.w;
        f_s[16 * PS + t] = fv4.x; f_s[17 * PS + t] = fv4.y; f_s[18 * PS + t] = fv4.z; f_s[19 * PS + t] = fv4.w;
        __syncthreads();

        // -------- M-step (tiled, float2-paired): 9 tiles of 3x7 (j,c),
        // 16 lanes/tile, each lane handles 2 adjacent pixels per iter (8 iters).
        float* __restrict__ dst = (mode == 1) ? g_partB : g_partA;
        if (t < 160) {
            const int tile = (t < 144) ? (t >> 4) : 8;  // lanes 16..31 of warp 4 duplicate tile 8
            const int g = t & 15;
            const int j0 = (tile / 3) * 3;
            const int c0 = (tile % 3) * 7;

            float acc[21];
            #pragma unroll
            for (int o = 0; o < 21; ++o) acc[o] = 0.0f;

            #pragma unroll 2
            for (int ii = 0; ii < 8; ++ii) {
                const int pix = ii * 32 + 2 * g;
                const float2 pj0 = *reinterpret_cast<const float2*>(&p_s[(j0 + 0) * PS + pix]);
                const float2 pj1 = *reinterpret_cast<const float2*>(&p_s[(j0 + 1) * PS + pix]);
                const float2 pj2 = *reinterpret_cast<const float2*>(&p_s[(j0 + 2) * PS + pix]);
                float2 fc[7];
                #pragma unroll
                for (int cc = 0; cc < 7; ++cc) {
                    const int c = c0 + cc;
                    fc[cc] = (c < CC) ? *reinterpret_cast<const float2*>(&f_s[c * PS + pix])
                                      : make_float2(1.0f, 1.0f);
                }
                #pragma unroll
                for (int cc = 0; cc < 7; ++cc) {
                    acc[cc]      = fmaf(pj0.x, fc[cc].x, fmaf(pj0.y, fc[cc].y, acc[cc]));
                    acc[7 + cc]  = fmaf(pj1.x, fc[cc].x, fmaf(pj1.y, fc[cc].y, acc[7 + cc]));
                    acc[14 + cc] = fmaf(pj2.x, fc[cc].x, fmaf(pj2.y, fc[cc].y, acc[14 + cc]));
                }
            }
            // half-warp butterfly (offsets < 16 stay within the 16-lane group)
            #pragma unroll
            for (int o = 0; o < 21; ++o) {
                #pragma unroll
                for (int off = 8; off >= 1; off >>= 1)
                    acc[o] += __shfl_xor_sync(0xffffffffu, acc[o], off);
            }
            if (t < 144) {
                const int base = ((b * KK + cell) * 9 + j0) * 21 + c0;
                {
                    const int jj = g / 7, cc = g % 7;
                    dst[base + jj * 21 + cc] = acc[g];
                }
                if (g < 5) {
                    const int o = g + 16;
                    const int jj = o / 7, cc = o % 7;
                    dst[base + jj * 21 + cc] = acc[o];
                }
            }
        }
    }
}

// ---------------------------------------------------------------------------
// FINAL: finalize mean from g_partA, E-step, expand to dense [B,N,K] output.
// grid=(K,B), 256 threads.
// ---------------------------------------------------------------------------
__global__ __launch_bounds__(256) void ssn_final(const float* __restrict__ feat,
                                                 float* __restrict__ out) {
    __shared__ float p_s[256 * 9];                      // p_s[pix][j]
    __shared__ __align__(16) float mean_s[9 * CC];
    __shared__ float msq_s[9];
    __shared__ float raw_s[9 * 21 + 3];

    const int b = blockIdx.y, cell = blockIdx.x, t = threadIdx.x;
    const int py = cell >> 4, px = cell & 15;

    // mean finalize from g_partA
    if (t < 9 * 21) {
        const int j = t / 21, c = t % 21;
        const int ky = py + j / 3 - 1, kx = px + j % 3 - 1;
        float s = 0.0f;
        if (ky >= 0 && ky < KGRID && kx >= 0 && kx < KGRID) {
            #pragma unroll
            for (int dy = -1; dy <= 1; ++dy)
                #pragma unroll
                for (int dx = -1; dx <= 1; ++dx) {
                    const int cy = ky + dy, cx = kx + dx;
                    if (cy >= 0 && cy < KGRID && cx >= 0 && cx < KGRID) {
                        const int jj = (ky - cy + 1) * 3 + (kx - cx + 1);
                        s += g_partA[((b * KK + cy * KGRID + cx) * 9 + jj) * 21 + c];
                    }
                }
        }
        raw_s[t] = s;
    }
    __syncthreads();
    if (t < 9 * CC) {
        const int j = t / CC, c = t % CC;
        mean_s[t] = raw_s[j * 21 + c] / fmaxf(raw_s[j * 21 + 20], 1e-12f);
    }
    __syncthreads();
    if (t < 9) {
        float s = 0.0f;
        #pragma unroll
        for (int c = 0; c < CC; ++c) { const float m = mean_s[t * CC + c]; s += m * m; }
        msq_s[t] = s;
    }
    __syncthreads();

    // E-step for this thread's pixel
    const int r = t >> 4, cc2 = t & 15;
    const int n = (py * CELLSZ + r) * HH + px * CELLSZ + cc2;
    const float4* fp = reinterpret_cast<const float4*>(feat + (size_t)(b * NN + n) * CC);
    float4 fv0 = fp[0], fv1 = fp[1], fv2 = fp[2], fv3 = fp[3], fv4 = fp[4];

    float s[9];
    float smax = -1e30f;
    #pragma unroll
    for (int j = 0; j < 9; ++j) {
        const int ky = py + j / 3 - 1, kx = px + j % 3 - 1;
        if (ky >= 0 && ky < KGRID && kx >= 0 && kx < KGRID) {
            const float4* mr = reinterpret_cast<const float4*>(mean_s + j * CC);
            float dot = 0.0f;
            float4 m;
            m = mr[0]; dot = fmaf(fv0.x,m.x,fmaf(fv0.y,m.y,fmaf(fv0.z,m.z,fmaf(fv0.w,m.w,dot))));
            m = mr[1]; dot = fmaf(fv1.x,m.x,fmaf(fv1.y,m.y,fmaf(fv1.z,m.z,fmaf(fv1.w,m.w,dot))));
            m = mr[2]; dot = fmaf(fv2.x,m.x,fmaf(fv2.y,m.y,fmaf(fv2.z,m.z,fmaf(fv2.w,m.w,dot))));
            m = mr[3]; dot = fmaf(fv3.x,m.x,fmaf(fv3.y,m.y,fmaf(fv3.z,m.z,fmaf(fv3.w,m.w,dot))));
            m = mr[4]; dot = fmaf(fv4.x,m.x,fmaf(fv4.y,m.y,fmaf(fv4.z,m.z,fmaf(fv4.w,m.w,dot))));
            s[j] = 2.0f * dot - msq_s[j];
            smax = fmaxf(smax, s[j]);
        } else {
            s[j] = -1e30f;
        }
    }
    float p[9], denom = 0.0f;
    #pragma unroll
    for (int j = 0; j < 9; ++j) {
        p[j] = (s[j] > -1e29f) ? __expf(s[j] - smax) : 0.0f;
        denom += p[j];
    }
    const float inv = 1.0f / denom;
    #pragma unroll
    for (int j = 0; j < 9; ++j) p_s[t * 9 + j] = p[j] * inv;
    __syncthreads();

    // Dense expansion: 64 iterations x (4 pixels x 64 float4s) = 256 pixels x 256 k
    const int sub = t >> 6;        // which of the 4 pixels this thread serves
    const int kq  = t & 63;        // float4 index within the k-row
    const int k0  = kq * 4;
    const int gy  = k0 >> 4;       // constant across the float4 (k0 % 16 <= 12)
    const int dy  = gy - py;
    const bool rowok = (dy >= -1 && dy <= 1);
    const int jbase = (dy + 1) * 3;
    const int gx0 = k0 & 15;

    for (int it = 0; it < 64; ++it) {
        const int pix = it * 4 + sub;
        const int rr = pix >> 4, cpx = pix & 15;
        const int n2 = (py * CELLSZ + rr) * HH + px * CELLSZ + cpx;
        const float* pr = &p_s[pix * 9];
        float4 v;
        {
            const int dx = gx0 + 0 - px;
            v.x = (rowok && dx >= -1 && dx <= 1) ? pr[jbase + dx + 1] : 0.0f;
        }
        {
            const int dx = gx0 + 1 - px;
            v.y = (rowok && dx >= -1 && dx <= 1) ? pr[jbase + dx + 1] : 0.0f;
        }
        {
            const int dx = gx0 + 2 - px;
            v.z = (rowok && dx >= -1 && dx <= 1) ? pr[jbase + dx + 1] : 0.0f;
        }
        {
            const int dx = gx0 + 3 - px;
            v.w = (rowok && dx >= -1 && dx <= 1) ? pr[jbase + dx + 1] : 0.0f;
        }
        reinterpret_cast<float4*>(out + (size_t)(b * NN + n2) * KK)[kq] = v;
    }
}

// ---------------------------------------------------------------------------
extern "C" void kernel_launch(void* const* d_in, const int* in_sizes, int n_in,
                              void* d_out, int out_size) {
    const float* feat = (const float*)d_in[0];
    float* out = (float*)d_out;
    (void)in_sizes; (void)n_in; (void)out_size;

    dim3 grid(KK, BN);

    ssn_init_mean<<<grid, 256>>>(feat);
    ssn_em_iter<<<EMGRID, 256>>>(feat, 0);
    for (int i = 0; i < 4; ++i) {
        ssn_em_iter<<<EMGRID, 256>>>(feat, 1);
        ssn_em_iter<<<EMGRID, 256>>>(feat, 2);
    }
    ssn_final<<<grid, 256>>>(feat, out);
}

// round 14
// speedup vs baseline: 1.1027x; 1.1027x over previous
#include <cuda_runtime.h>

// SSN superpixel EM, sparse 9-neighborhood formulation.
// B=4, H=W=256, C=20, 16x16 superpixel grid, cell=16x16, K=256, 10 EM iters.

#define BN     4
#define HH     256
#define NN     (HH*HH)      // 65536 pixels
#define CC     20
#define KGRID  16
#define KK     (KGRID*KGRID)
#define CELLSZ 16
#define PS     260          // stride (floats): 260*4B = 65*16B -> every row 16B-aligned, conflict-free stride-1

// Scratch (device globals: no allocation allowed)
__device__ float g_mean[BN * KK * CC];
__device__ float g_partA[BN * KK * 9 * 21];
__device__ float g_partB[BN * KK * 9 * 21];

// ---------------------------------------------------------------------------
// INIT: mean of features within each initial 16x16 cell. grid=(K,B), 256 thr.
// ---------------------------------------------------------------------------
__global__ __launch_bounds__(256) void ssn_init_mean(const float* __restrict__ feat) {
    const int b = blockIdx.y, cell = blockIdx.x, t = threadIdx.x;
    const int py = cell >> 4, px = cell & 15;
    const int r = t >> 4, cc = t & 15;
    const int n = (py * CELLSZ + r) * HH + px * CELLSZ + cc;

    const float4* fp = reinterpret_cast<const float4*>(feat + (size_t)(b * NN + n) * CC);
    float f[CC];
    {
        float4 v;
        v = fp[0]; f[0]=v.x; f[1]=v.y; f[2]=v.z; f[3]=v.w;
        v = fp[1]; f[4]=v.x; f[5]=v.y; f[6]=v.z; f[7]=v.w;
        v = fp[2]; f[8]=v.x; f[9]=v.y; f[10]=v.z; f[11]=v.w;
        v = fp[3]; f[12]=v.x; f[13]=v.y; f[14]=v.z; f[15]=v.w;
        v = fp[4]; f[16]=v.x; f[17]=v.y; f[18]=v.z; f[19]=v.w;
    }

    __shared__ float ssum[CC];
    if (t < CC) ssum[t] = 0.0f;
    __syncthreads();

    const int lane = t & 31;
    #pragma unroll
    for (int c = 0; c < CC; ++c) {
        float v = f[c];
        #pragma unroll
        for (int off = 16; off > 0; off >>= 1)
            v += __shfl_xor_sync(0xffffffffu, v, off);
        if (lane == 0) atomicAdd(&ssum[c], v);
    }
    __syncthreads();
    if (t < CC) g_mean[(b * KK + cell) * CC + t] = ssum[t] * (1.0f / 256.0f);
}

// ---------------------------------------------------------------------------
// EM iteration (fused mean-finalize + E-step + tiled M-step, float4 strips).
// mode: 0 = read g_mean, write g_partA
//       1 = read g_partA, write g_partB
//       2 = read g_partB, write g_partA
// grid=(K,B) blocks of 256 (block = one 16x16 cell of one batch).
// ---------------------------------------------------------------------------
__global__ __launch_bounds__(256, 5) void ssn_em_iter(const float* __restrict__ feat, int mode) {
    __shared__ __align__(16) float p_s[9 * PS];         // p_s[j][pix]
    __shared__ __align__(16) float f_s[CC * PS];        // f_s[c][pix]
    __shared__ __align__(16) float mean_s[9 * CC];      // float4-read (rows 80B)
    __shared__ float msq_s[9];
    __shared__ float raw_s[9 * 21 + 3];

    const int b = blockIdx.y, cell = blockIdx.x, t = threadIdx.x;
    const int py = cell >> 4, px = cell & 15;

    // -------- prologue: assemble the 9 neighbor-superpixel means --------
    if (mode == 0) {
        if (t < 9 * CC) {
            const int j = t / CC, c = t % CC;
            const int ky = py + j / 3 - 1, kx = px + j % 3 - 1;
            float m = 0.0f;
            if (ky >= 0 && ky < KGRID && kx >= 0 && kx < KGRID)
                m = g_mean[(b * KK + ky * KGRID + kx) * CC + c];
            mean_s[t] = m;
        }
    } else {
        const float* __restrict__ src = (mode == 1) ? g_partA : g_partB;
        if (t < 9 * 21) {
            const int j = t / 21, c = t % 21;
            const int ky = py + j / 3 - 1, kx = px + j % 3 - 1;
            float s = 0.0f;
            if (ky >= 0 && ky < KGRID && kx >= 0 && kx < KGRID) {
                #pragma unroll
                for (int dy = -1; dy <= 1; ++dy)
                    #pragma unroll
                    for (int dx = -1; dx <= 1; ++dx) {
                        const int cy = ky + dy, cx = kx + dx;
                        if (cy >= 0 && cy < KGRID && cx >= 0 && cx < KGRID) {
                            const int jj = (ky - cy + 1) * 3 + (kx - cx + 1);
                            s += src[((b * KK + cy * KGRID + cx) * 9 + jj) * 21 + c];
                        }
                    }
            }
            raw_s[t] = s;
        }
        __syncthreads();
        if (t < 9 * CC) {
            const int j = t / CC, c = t % CC;
            mean_s[t] = raw_s[j * 21 + c] / fmaxf(raw_s[j * 21 + 20], 1e-12f);
        }
    }
    __syncthreads();
    if (t < 9) {
        float s = 0.0f;
        #pragma unroll
        for (int c = 0; c < CC; ++c) { const float m = mean_s[t * CC + c]; s += m * m; }
        msq_s[t] = s;
    }
    __syncthreads();

    // -------- E-step: one pixel per thread --------
    // softmax(-dist) invariant to ||f||^2: p[j] ∝ exp(2*dot_j - msq_j).
    const int r = t >> 4, cc2 = t & 15;
    const int n = (py * CELLSZ + r) * HH + px * CELLSZ + cc2;
    const float4* fp = reinterpret_cast<const float4*>(feat + (size_t)(b * NN + n) * CC);
    float4 fv0 = fp[0], fv1 = fp[1], fv2 = fp[2], fv3 = fp[3], fv4 = fp[4];

    float s[9];
    float smax = -1e30f;
    #pragma unroll
    for (int j = 0; j < 9; ++j) {
        const int ky = py + j / 3 - 1, kx = px + j % 3 - 1;
        if (ky >= 0 && ky < KGRID && kx >= 0 && kx < KGRID) {
            const float4* mr = reinterpret_cast<const float4*>(mean_s + j * CC);
            float dot = 0.0f;
            float4 m;
            m = mr[0]; dot = fmaf(fv0.x,m.x,fmaf(fv0.y,m.y,fmaf(fv0.z,m.z,fmaf(fv0.w,m.w,dot))));
            m = mr[1]; dot = fmaf(fv1.x,m.x,fmaf(fv1.y,m.y,fmaf(fv1.z,m.z,fmaf(fv1.w,m.w,dot))));
            m = mr[2]; dot = fmaf(fv2.x,m.x,fmaf(fv2.y,m.y,fmaf(fv2.z,m.z,fmaf(fv2.w,m.w,dot))));
            m = mr[3]; dot = fmaf(fv3.x,m.x,fmaf(fv3.y,m.y,fmaf(fv3.z,m.z,fmaf(fv3.w,m.w,dot))));
            m = mr[4]; dot = fmaf(fv4.x,m.x,fmaf(fv4.y,m.y,fmaf(fv4.z,m.z,fmaf(fv4.w,m.w,dot))));
            s[j] = 2.0f * dot - msq_s[j];
            smax = fmaxf(smax, s[j]);
        } else {
            s[j] = -1e30f;
        }
    }
    float p[9], denom = 0.0f;
    #pragma unroll
    for (int j = 0; j < 9; ++j) {
        p[j] = (s[j] > -1e29f) ? __expf(s[j] - smax) : 0.0f;
        denom += p[j];
    }
    const float inv = 1.0f / denom;   // denom >= 1 (argmax contributes exp(0)=1)
    #pragma unroll
    for (int j = 0; j < 9; ++j) p_s[j * PS + t] = p[j] * inv;
    f_s[ 0 * PS + t] = fv0.x; f_s[ 1 * PS + t] = fv0.y; f_s[ 2 * PS + t] = fv0.z; f_s[ 3 * PS + t] = fv0.w;
    f_s[ 4 * PS + t] = fv1.x; f_s[ 5 * PS + t] = fv1.y; f_s[ 6 * PS + t] = fv1.z; f_s[ 7 * PS + t] = fv1.w;
    f_s[ 8 * PS + t] = fv2.x; f_s[ 9 * PS + t] = fv2.y; f_s[10 * PS + t] = fv2.z; f_s[11 * PS + t] = fv2.w;
    f_s[12 * PS + t] = fv3.x; f_s[13 * PS + t] = fv3.y; f_s[14 * PS + t] = fv3.z; f_s[15 * PS + t] = fv3.w;
    f_s[16 * PS + t] = fv4.x; f_s[17 * PS + t] = fv4.y; f_s[18 * PS + t] = fv4.z; f_s[19 * PS + t] = fv4.w;
    __syncthreads();

    // -------- M-step (tiled, float4 strips): 9 tiles of 3x7 (j,c),
    // 16 lanes/tile, each lane handles 4 adjacent pixels per iter (4 iters).
    // LDS.128 at 16B-consecutive lane addresses -> conflict-free.
    float* __restrict__ dst = (mode == 1) ? g_partB : g_partA;
    if (t < 160) {
        const int tile = (t < 144) ? (t >> 4) : 8;  // lanes 16..31 of warp 4 duplicate tile 8
        const int g = t & 15;
        const int j0 = (tile / 3) * 3;
        const int c0 = (tile % 3) * 7;

        float acc[21];
        #pragma unroll
        for (int o = 0; o < 21; ++o) acc[o] = 0.0f;

        #pragma unroll 2
        for (int ii = 0; ii < 4; ++ii) {
            const int pix = ii * 64 + 4 * g;
            const float4 pj0 = *reinterpret_cast<const float4*>(&p_s[(j0 + 0) * PS + pix]);
            const float4 pj1 = *reinterpret_cast<const float4*>(&p_s[(j0 + 1) * PS + pix]);
            const float4 pj2 = *reinterpret_cast<const float4*>(&p_s[(j0 + 2) * PS + pix]);
            #pragma unroll
            for (int cc = 0; cc < 7; ++cc) {
                const int c = c0 + cc;
                const float4 fc = (c < CC)
                    ? *reinterpret_cast<const float4*>(&f_s[c * PS + pix])
                    : make_float4(1.0f, 1.0f, 1.0f, 1.0f);
                acc[cc]      = fmaf(pj0.x, fc.x, fmaf(pj0.y, fc.y, fmaf(pj0.z, fc.z, fmaf(pj0.w, fc.w, acc[cc]))));
                acc[7 + cc]  = fmaf(pj1.x, fc.x, fmaf(pj1.y, fc.y, fmaf(pj1.z, fc.z, fmaf(pj1.w, fc.w, acc[7 + cc]))));
                acc[14 + cc] = fmaf(pj2.x, fc.x, fmaf(pj2.y, fc.y, fmaf(pj2.z, fc.z, fmaf(pj2.w, fc.w, acc[14 + cc]))));
            }
        }
        // half-warp butterfly (offsets < 16 stay within the 16-lane group)
        #pragma unroll
        for (int o = 0; o < 21; ++o) {
            #pragma unroll
            for (int off = 8; off >= 1; off >>= 1)
                acc[o] += __shfl_xor_sync(0xffffffffu, acc[o], off);
        }
        if (t < 144) {
            const int base = ((b * KK + cell) * 9 + j0) * 21 + c0;
            {
                const int jj = g / 7, cc = g % 7;
                dst[base + jj * 21 + cc] = acc[g];
            }
            if (g < 5) {
                const int o = g + 16;
                const int jj = o / 7, cc = o % 7;
                dst[base + jj * 21 + cc] = acc[o];
            }
        }
    }
}

// ---------------------------------------------------------------------------
// FINAL: finalize mean from g_partA, E-step, expand to dense [B,N,K] output.
// grid=(K,B), 256 threads.
// ---------------------------------------------------------------------------
__global__ __launch_bounds__(256) void ssn_final(const float* __restrict__ feat,
                                                 float* __restrict__ out) {
    __shared__ float p_s[256 * 9];                      // p_s[pix][j]
    __shared__ __align__(16) float mean_s[9 * CC];
    __shared__ float msq_s[9];
    __shared__ float raw_s[9 * 21 + 3];

    const int b = blockIdx.y, cell = blockIdx.x, t = threadIdx.x;
    const int py = cell >> 4, px = cell & 15;

    // mean finalize from g_partA
    if (t < 9 * 21) {
        const int j = t / 21, c = t % 21;
        const int ky = py + j / 3 - 1, kx = px + j % 3 - 1;
        float s = 0.0f;
        if (ky >= 0 && ky < KGRID && kx >= 0 && kx < KGRID) {
            #pragma unroll
            for (int dy = -1; dy <= 1; ++dy)
                #pragma unroll
                for (int dx = -1; dx <= 1; ++dx) {
                    const int cy = ky + dy, cx = kx + dx;
                    if (cy >= 0 && cy < KGRID && cx >= 0 && cx < KGRID) {
                        const int jj = (ky - cy + 1) * 3 + (kx - cx + 1);
                        s += g_partA[((b * KK + cy * KGRID + cx) * 9 + jj) * 21 + c];
                    }
                }
        }
        raw_s[t] = s;
    }
    __syncthreads();
    if (t < 9 * CC) {
        const int j = t / CC, c = t % CC;
        mean_s[t] = raw_s[j * 21 + c] / fmaxf(raw_s[j * 21 + 20], 1e-12f);
    }
    __syncthreads();
    if (t < 9) {
        float s = 0.0f;
        #pragma unroll
        for (int c = 0; c < CC; ++c) { const float m = mean_s[t * CC + c]; s += m * m; }
        msq_s[t] = s;
    }
    __syncthreads();

    // E-step for this thread's pixel
    const int r = t >> 4, cc2 = t & 15;
    const int n = (py * CELLSZ + r) * HH + px * CELLSZ + cc2;
    const float4* fp = reinterpret_cast<const float4*>(feat + (size_t)(b * NN + n) * CC);
    float4 fv0 = fp[0], fv1 = fp[1], fv2 = fp[2], fv3 = fp[3], fv4 = fp[4];

    float s[9];
    float smax = -1e30f;
    #pragma unroll
    for (int j = 0; j < 9; ++j) {
        const int ky = py + j / 3 - 1, kx = px + j % 3 - 1;
        if (ky >= 0 && ky < KGRID && kx >= 0 && kx < KGRID) {
            const float4* mr = reinterpret_cast<const float4*>(mean_s + j * CC);
            float dot = 0.0f;
            float4 m;
            m = mr[0]; dot = fmaf(fv0.x,m.x,fmaf(fv0.y,m.y,fmaf(fv0.z,m.z,fmaf(fv0.w,m.w,dot))));
            m = mr[1]; dot = fmaf(fv1.x,m.x,fmaf(fv1.y,m.y,fmaf(fv1.z,m.z,fmaf(fv1.w,m.w,dot))));
            m = mr[2]; dot = fmaf(fv2.x,m.x,fmaf(fv2.y,m.y,fmaf(fv2.z,m.z,fmaf(fv2.w,m.w,dot))));
            m = mr[3]; dot = fmaf(fv3.x,m.x,fmaf(fv3.y,m.y,fmaf(fv3.z,m.z,fmaf(fv3.w,m.w,dot))));
            m = mr[4]; dot = fmaf(fv4.x,m.x,fmaf(fv4.y,m.y,fmaf(fv4.z,m.z,fmaf(fv4.w,m.w,dot))));
            s[j] = 2.0f * dot - msq_s[j];
            smax = fmaxf(smax, s[j]);
        } else {
            s[j] = -1e30f;
        }
    }
    float p[9], denom = 0.0f;
    #pragma unroll
    for (int j = 0; j < 9; ++j) {
        p[j] = (s[j] > -1e29f) ? __expf(s[j] - smax) : 0.0f;
        denom += p[j];
    }
    const float inv = 1.0f / denom;
    #pragma unroll
    for (int j = 0; j < 9; ++j) p_s[t * 9 + j] = p[j] * inv;
    __syncthreads();

    // Dense expansion: 64 iterations x (4 pixels x 64 float4s) = 256 pixels x 256 k
    const int sub = t >> 6;        // which of the 4 pixels this thread serves
    const int kq  = t & 63;        // float4 index within the k-row
    const int k0  = kq * 4;
    const int gy  = k0 >> 4;       // constant across the float4 (k0 % 16 <= 12)
    const int dy  = gy - py;
    const bool rowok = (dy >= -1 && dy <= 1);
    const int jbase = (dy + 1) * 3;
    const int gx0 = k0 & 15;

    for (int it = 0; it < 64; ++it) {
        const int pix = it * 4 + sub;
        const int rr = pix >> 4, cpx = pix & 15;
        const int n2 = (py * CELLSZ + rr) * HH + px * CELLSZ + cpx;
        const float* pr = &p_s[pix * 9];
        float4 v;
        {
            const int dx = gx0 + 0 - px;
            v.x = (rowok && dx >= -1 && dx <= 1) ? pr[jbase + dx + 1] : 0.0f;
        }
        {
            const int dx = gx0 + 1 - px;
            v.y = (rowok && dx >= -1 && dx <= 1) ? pr[jbase + dx + 1] : 0.0f;
        }
        {
            const int dx = gx0 + 2 - px;
            v.z = (rowok && dx >= -1 && dx <= 1) ? pr[jbase + dx + 1] : 0.0f;
        }
        {
            const int dx = gx0 + 3 - px;
            v.w = (rowok && dx >= -1 && dx <= 1) ? pr[jbase + dx + 1] : 0.0f;
        }
        reinterpret_cast<float4*>(out + (size_t)(b * NN + n2) * KK)[kq] = v;
    }
}

// ---------------------------------------------------------------------------
extern "C" void kernel_launch(void* const* d_in, const int* in_sizes, int n_in,
                              void* d_out, int out_size) {
    const float* feat = (const float*)d_in[0];
    float* out = (float*)d_out;
    (void)in_sizes; (void)n_in; (void)out_size;

    dim3 grid(KK, BN);

    ssn_init_mean<<<grid, 256>>>(feat);
    ssn_em_iter<<<grid, 256>>>(feat, 0);
    for (int i = 0; i < 4; ++i) {
        ssn_em_iter<<<grid, 256>>>(feat, 1);
        ssn_em_iter<<<grid, 256>>>(feat, 2);
    }
    ssn_final<<<grid, 256>>>(feat, out);
}

// round 17
// speedup vs baseline: 1.1756x; 1.0661x over previous
#include <cuda_runtime.h>

// SSN superpixel EM, sparse 9-neighborhood formulation.
// B=4, H=W=256, C=20, 16x16 superpixel grid, cell=16x16, K=256, 10 EM iters.

#define BN     4
#define HH     256
#define NN     (HH*HH)      // 65536 pixels
#define CC     20
#define KGRID  16
#define KK     (KGRID*KGRID)
#define CELLSZ 16
#define PS     260          // stride (floats): 260*4B = 65*16B -> every row 16B-aligned, conflict-free stride-1

// Scratch (device globals: no allocation allowed)
__device__ float g_mean[BN * KK * CC];
__device__ float g_partA[BN * KK * 9 * 21];
__device__ float g_partB[BN * KK * 9 * 21];

// ---------------------------------------------------------------------------
// INIT: mean of features within each initial 16x16 cell. grid=(K,B), 256 thr.
// ---------------------------------------------------------------------------
__global__ __launch_bounds__(256) void ssn_init_mean(const float* __restrict__ feat) {
    const int b = blockIdx.y, cell = blockIdx.x, t = threadIdx.x;
    const int py = cell >> 4, px = cell & 15;
    const int r = t >> 4, cc = t & 15;
    const int n = (py * CELLSZ + r) * HH + px * CELLSZ + cc;

    const float4* fp = reinterpret_cast<const float4*>(feat + (size_t)(b * NN + n) * CC);
    float f[CC];
    {
        float4 v;
        v = fp[0]; f[0]=v.x; f[1]=v.y; f[2]=v.z; f[3]=v.w;
        v = fp[1]; f[4]=v.x; f[5]=v.y; f[6]=v.z; f[7]=v.w;
        v = fp[2]; f[8]=v.x; f[9]=v.y; f[10]=v.z; f[11]=v.w;
        v = fp[3]; f[12]=v.x; f[13]=v.y; f[14]=v.z; f[15]=v.w;
        v = fp[4]; f[16]=v.x; f[17]=v.y; f[18]=v.z; f[19]=v.w;
    }

    __shared__ float ssum[CC];
    if (t < CC) ssum[t] = 0.0f;
    __syncthreads();

    const int lane = t & 31;
    #pragma unroll
    for (int c = 0; c < CC; ++c) {
        float v = f[c];
        #pragma unroll
        for (int off = 16; off > 0; off >>= 1)
            v += __shfl_xor_sync(0xffffffffu, v, off);
        if (lane == 0) atomicAdd(&ssum[c], v);
    }
    __syncthreads();
    if (t < CC) g_mean[(b * KK + cell) * CC + t] = ssum[t] * (1.0f / 256.0f);
}

// ---------------------------------------------------------------------------
// EM iteration (fused mean-finalize + E-step + tiled M-step, float4 strips).
// Feature loads hoisted to kernel entry so their latency overlaps the
// prologue's scattered loads + barriers.
// mode: 0 = read g_mean, write g_partA
//       1 = read g_partA, write g_partB
//       2 = read g_partB, write g_partA
// grid=(K,B) blocks of 256 (block = one 16x16 cell of one batch).
// ---------------------------------------------------------------------------
__global__ __launch_bounds__(256, 5) void ssn_em_iter(const float* __restrict__ feat, int mode) {
    __shared__ __align__(16) float p_s[9 * PS];         // p_s[j][pix]
    __shared__ __align__(16) float f_s[CC * PS];        // f_s[c][pix]
    __shared__ __align__(16) float mean_s[9 * CC];      // float4-read (rows 80B)
    __shared__ float msq_s[9];
    __shared__ float raw_s[9 * 21 + 3];

    const int b = blockIdx.y, cell = blockIdx.x, t = threadIdx.x;
    const int py = cell >> 4, px = cell & 15;

    // -------- hoisted feature load (overlaps entire prologue) --------
    const int r = t >> 4, cc2 = t & 15;
    const int n = (py * CELLSZ + r) * HH + px * CELLSZ + cc2;
    const float4* fp = reinterpret_cast<const float4*>(feat + (size_t)(b * NN + n) * CC);
    const float4 fv0 = fp[0], fv1 = fp[1], fv2 = fp[2], fv3 = fp[3], fv4 = fp[4];

    // -------- prologue: assemble the 9 neighbor-superpixel means --------
    if (mode == 0) {
        if (t < 9 * CC) {
            const int j = t / CC, c = t % CC;
            const int ky = py + j / 3 - 1, kx = px + j % 3 - 1;
            float m = 0.0f;
            if (ky >= 0 && ky < KGRID && kx >= 0 && kx < KGRID)
                m = g_mean[(b * KK + ky * KGRID + kx) * CC + c];
            mean_s[t] = m;
        }
    } else {
        const float* __restrict__ src = (mode == 1) ? g_partA : g_partB;
        if (t < 9 * 21) {
            const int j = t / 21, c = t % 21;
            const int ky = py + j / 3 - 1, kx = px + j % 3 - 1;
            float s = 0.0f;
            if (ky >= 0 && ky < KGRID && kx >= 0 && kx < KGRID) {
                #pragma unroll
                for (int dy = -1; dy <= 1; ++dy)
                    #pragma unroll
                    for (int dx = -1; dx <= 1; ++dx) {
                        const int cy = ky + dy, cx = kx + dx;
                        if (cy >= 0 && cy < KGRID && cx >= 0 && cx < KGRID) {
                            const int jj = (ky - cy + 1) * 3 + (kx - cx + 1);
                            s += src[((b * KK + cy * KGRID + cx) * 9 + jj) * 21 + c];
                        }
                    }
            }
            raw_s[t] = s;
        }
        __syncthreads();
        if (t < 9 * CC) {
            const int j = t / CC, c = t % CC;
            mean_s[t] = raw_s[j * 21 + c] / fmaxf(raw_s[j * 21 + 20], 1e-12f);
        }
    }
    __syncthreads();
    if (t < 9) {
        float s = 0.0f;
        #pragma unroll
        for (int c = 0; c < CC; ++c) { const float m = mean_s[t * CC + c]; s += m * m; }
        msq_s[t] = s;
    }
    __syncthreads();

    // -------- E-step: one pixel per thread --------
    // softmax(-dist) invariant to ||f||^2: p[j] ∝ exp(2*dot_j - msq_j).
    float s[9];
    float smax = -1e30f;
    #pragma unroll
    for (int j = 0; j < 9; ++j) {
        const int ky = py + j / 3 - 1, kx = px + j % 3 - 1;
        if (ky >= 0 && ky < KGRID && kx >= 0 && kx < KGRID) {
            const float4* mr = reinterpret_cast<const float4*>(mean_s + j * CC);
            float dot = 0.0f;
            float4 m;
            m = mr[0]; dot = fmaf(fv0.x,m.x,fmaf(fv0.y,m.y,fmaf(fv0.z,m.z,fmaf(fv0.w,m.w,dot))));
            m = mr[1]; dot = fmaf(fv1.x,m.x,fmaf(fv1.y,m.y,fmaf(fv1.z,m.z,fmaf(fv1.w,m.w,dot))));
            m = mr[2]; dot = fmaf(fv2.x,m.x,fmaf(fv2.y,m.y,fmaf(fv2.z,m.z,fmaf(fv2.w,m.w,dot))));
            m = mr[3]; dot = fmaf(fv3.x,m.x,fmaf(fv3.y,m.y,fmaf(fv3.z,m.z,fmaf(fv3.w,m.w,dot))));
            m = mr[4]; dot = fmaf(fv4.x,m.x,fmaf(fv4.y,m.y,fmaf(fv4.z,m.z,fmaf(fv4.w,m.w,dot))));
            s[j] = 2.0f * dot - msq_s[j];
            smax = fmaxf(smax, s[j]);
        } else {
            s[j] = -1e30f;
        }
    }
    float p[9], denom = 0.0f;
    #pragma unroll
    for (int j = 0; j < 9; ++j) {
        p[j] = (s[j] > -1e29f) ? __expf(s[j] - smax) : 0.0f;
        denom += p[j];
    }
    const float inv = 1.0f / denom;   // denom >= 1 (argmax contributes exp(0)=1)
    #pragma unroll
    for (int j = 0; j < 9; ++j) p_s[j * PS + t] = p[j] * inv;
    f_s[ 0 * PS + t] = fv0.x; f_s[ 1 * PS + t] = fv0.y; f_s[ 2 * PS + t] = fv0.z; f_s[ 3 * PS + t] = fv0.w;
    f_s[ 4 * PS + t] = fv1.x; f_s[ 5 * PS + t] = fv1.y; f_s[ 6 * PS + t] = fv1.z; f_s[ 7 * PS + t] = fv1.w;
    f_s[ 8 * PS + t] = fv2.x; f_s[ 9 * PS + t] = fv2.y; f_s[10 * PS + t] = fv2.z; f_s[11 * PS + t] = fv2.w;
    f_s[12 * PS + t] = fv3.x; f_s[13 * PS + t] = fv3.y; f_s[14 * PS + t] = fv3.z; f_s[15 * PS + t] = fv3.w;
    f_s[16 * PS + t] = fv4.x; f_s[17 * PS + t] = fv4.y; f_s[18 * PS + t] = fv4.z; f_s[19 * PS + t] = fv4.w;
    __syncthreads();

    // -------- M-step (tiled, float4 strips): 9 tiles of 3x7 (j,c),
    // 16 lanes/tile, each lane handles 4 adjacent pixels per iter (4 iters).
    // LDS.128 at 16B-consecutive lane addresses -> conflict-free.
    float* __restrict__ dst = (mode == 1) ? g_partB : g_partA;
    if (t < 160) {
        const int tile = (t < 144) ? (t >> 4) : 8;  // lanes 16..31 of warp 4 duplicate tile 8
        const int g = t & 15;
        const int j0 = (tile / 3) * 3;
        const int c0 = (tile % 3) * 7;

        float acc[21];
        #pragma unroll
        for (int o = 0; o < 21; ++o) acc[o] = 0.0f;

        #pragma unroll 2
        for (int ii = 0; ii < 4; ++ii) {
            const int pix = ii * 64 + 4 * g;
            const float4 pj0 = *reinterpret_cast<const float4*>(&p_s[(j0 + 0) * PS + pix]);
            const float4 pj1 = *reinterpret_cast<const float4*>(&p_s[(j0 + 1) * PS + pix]);
            const float4 pj2 = *reinterpret_cast<const float4*>(&p_s[(j0 + 2) * PS + pix]);
            #pragma unroll
            for (int cc = 0; cc < 7; ++cc) {
                const int c = c0 + cc;
                const float4 fc = (c < CC)
                    ? *reinterpret_cast<const float4*>(&f_s[c * PS + pix])
                    : make_float4(1.0f, 1.0f, 1.0f, 1.0f);
                acc[cc]      = fmaf(pj0.x, fc.x, fmaf(pj0.y, fc.y, fmaf(pj0.z, fc.z, fmaf(pj0.w, fc.w, acc[cc]))));
                acc[7 + cc]  = fmaf(pj1.x, fc.x, fmaf(pj1.y, fc.y, fmaf(pj1.z, fc.z, fmaf(pj1.w, fc.w, acc[7 + cc]))));
                acc[14 + cc] = fmaf(pj2.x, fc.x, fmaf(pj2.y, fc.y, fmaf(pj2.z, fc.z, fmaf(pj2.w, fc.w, acc[14 + cc]))));
            }
        }
        // half-warp butterfly (offsets < 16 stay within the 16-lane group)
        #pragma unroll
        for (int o = 0; o < 21; ++o) {
            #pragma unroll
            for (int off = 8; off >= 1; off >>= 1)
                acc[o] += __shfl_xor_sync(0xffffffffu, acc[o], off);
        }
        if (t < 144) {
            const int base = ((b * KK + cell) * 9 + j0) * 21 + c0;
            {
                const int jj = g / 7, cc = g % 7;
                dst[base + jj * 21 + cc] = acc[g];
            }
            if (g < 5) {
                const int o = g + 16;
                const int jj = o / 7, cc = o % 7;
                dst[base + jj * 21 + cc] = acc[o];
            }
        }
    }
}

// ---------------------------------------------------------------------------
// FINAL: finalize mean from g_partA, E-step, expand to dense [B,N,K] output.
// grid=(K,B), 256 threads.
// ---------------------------------------------------------------------------
__global__ __launch_bounds__(256) void ssn_final(const float* __restrict__ feat,
                                                 float* __restrict__ out) {
    __shared__ float p_s[256 * 9];                      // p_s[pix][j]
    __shared__ __align__(16) float mean_s[9 * CC];
    __shared__ float msq_s[9];
    __shared__ float raw_s[9 * 21 + 3];

    const int b = blockIdx.y, cell = blockIdx.x, t = threadIdx.x;
    const int py = cell >> 4, px = cell & 15;

    // hoisted feature load (overlaps prologue)
    const int r = t >> 4, cc2 = t & 15;
    const int n = (py * CELLSZ + r) * HH + px * CELLSZ + cc2;
    const float4* fp = reinterpret_cast<const float4*>(feat + (size_t)(b * NN + n) * CC);
    const float4 fv0 = fp[0], fv1 = fp[1], fv2 = fp[2], fv3 = fp[3], fv4 = fp[4];

    // mean finalize from g_partA
    if (t < 9 * 21) {
        const int j = t / 21, c = t % 21;
        const int ky = py + j / 3 - 1, kx = px + j % 3 - 1;
        float s = 0.0f;
        if (ky >= 0 && ky < KGRID && kx >= 0 && kx < KGRID) {
            #pragma unroll
            for (int dy = -1; dy <= 1; ++dy)
                #pragma unroll
                for (int dx = -1; dx <= 1; ++dx) {
                    const int cy = ky + dy, cx = kx + dx;
                    if (cy >= 0 && cy < KGRID && cx >= 0 && cx < KGRID) {
                        const int jj = (ky - cy + 1) * 3 + (kx - cx + 1);
                        s += g_partA[((b * KK + cy * KGRID + cx) * 9 + jj) * 21 + c];
                    }
                }
        }
        raw_s[t] = s;
    }
    __syncthreads();
    if (t < 9 * CC) {
        const int j = t / CC, c = t % CC;
        mean_s[t] = raw_s[j * 21 + c] / fmaxf(raw_s[j * 21 + 20], 1e-12f);
    }
    __syncthreads();
    if (t < 9) {
        float s = 0.0f;
        #pragma unroll
        for (int c = 0; c < CC; ++c) { const float m = mean_s[t * CC + c]; s += m * m; }
        msq_s[t] = s;
    }
    __syncthreads();

    // E-step for this thread's pixel
    float s[9];
    float smax = -1e30f;
    #pragma unroll
    for (int j = 0; j < 9; ++j) {
        const int ky = py + j / 3 - 1, kx = px + j % 3 - 1;
        if (ky >= 0 && ky < KGRID && kx >= 0 && kx < KGRID) {
            const float4* mr = reinterpret_cast<const float4*>(mean_s + j * CC);
            float dot = 0.0f;
            float4 m;
            m = mr[0]; dot = fmaf(fv0.x,m.x,fmaf(fv0.y,m.y,fmaf(fv0.z,m.z,fmaf(fv0.w,m.w,dot))));
            m = mr[1]; dot = fmaf(fv1.x,m.x,fmaf(fv1.y,m.y,fmaf(fv1.z,m.z,fmaf(fv1.w,m.w,dot))));
            m = mr[2]; dot = fmaf(fv2.x,m.x,fmaf(fv2.y,m.y,fmaf(fv2.z,m.z,fmaf(fv2.w,m.w,dot))));
            m = mr[3]; dot = fmaf(fv3.x,m.x,fmaf(fv3.y,m.y,fmaf(fv3.z,m.z,fmaf(fv3.w,m.w,dot))));
            m = mr[4]; dot = fmaf(fv4.x,m.x,fmaf(fv4.y,m.y,fmaf(fv4.z,m.z,fmaf(fv4.w,m.w,dot))));
            s[j] = 2.0f * dot - msq_s[j];
            smax = fmaxf(smax, s[j]);
        } else {
            s[j] = -1e30f;
        }
    }
    float p[9], denom = 0.0f;
    #pragma unroll
    for (int j = 0; j < 9; ++j) {
        p[j] = (s[j] > -1e29f) ? __expf(s[j] - smax) : 0.0f;
        denom += p[j];
    }
    const float inv = 1.0f / denom;
    #pragma unroll
    for (int j = 0; j < 9; ++j) p_s[t * 9 + j] = p[j] * inv;
    __syncthreads();

    // Dense expansion: 64 iterations x (4 pixels x 64 float4s) = 256 pixels x 256 k
    const int sub = t >> 6;        // which of the 4 pixels this thread serves
    const int kq  = t & 63;        // float4 index within the k-row
    const int k0  = kq * 4;
    const int gy  = k0 >> 4;       // constant across the float4 (k0 % 16 <= 12)
    const int dy  = gy - py;
    const bool rowok = (dy >= -1 && dy <= 1);
    const int jbase = (dy + 1) * 3;
    const int gx0 = k0 & 15;

    for (int it = 0; it < 64; ++it) {
        const int pix = it * 4 + sub;
        const int rr = pix >> 4, cpx = pix & 15;
        const int n2 = (py * CELLSZ + rr) * HH + px * CELLSZ + cpx;
        const float* pr = &p_s[pix * 9];
        float4 v;
        {
            const int dx = gx0 + 0 - px;
            v.x = (rowok && dx >= -1 && dx <= 1) ? pr[jbase + dx + 1] : 0.0f;
        }
        {
            const int dx = gx0 + 1 - px;
            v.y = (rowok && dx >= -1 && dx <= 1) ? pr[jbase + dx + 1] : 0.0f;
        }
        {
            const int dx = gx0 + 2 - px;
            v.z = (rowok && dx >= -1 && dx <= 1) ? pr[jbase + dx + 1] : 0.0f;
        }
        {
            const int dx = gx0 + 3 - px;
            v.w = (rowok && dx >= -1 && dx <= 1) ? pr[jbase + dx + 1] : 0.0f;
        }
        reinterpret_cast<float4*>(out + (size_t)(b * NN + n2) * KK)[kq] = v;
    }
}

// ---------------------------------------------------------------------------
extern "C" void kernel_launch(void* const* d_in, const int* in_sizes, int n_in,
                              void* d_out, int out_size) {
    const float* feat = (const float*)d_in[0];
    float* out = (float*)d_out;
    (void)in_sizes; (void)n_in; (void)out_size;

    dim3 grid(KK, BN);

    ssn_init_mean<<<grid, 256>>>(feat);
    ssn_em_iter<<<grid, 256>>>(feat, 0);
    for (int i = 0; i < 4; ++i) {
        ssn_em_iter<<<grid, 256>>>(feat, 1);
        ssn_em_iter<<<grid, 256>>>(feat, 2);
    }
    ssn_final<<<grid, 256>>>(feat, out);
}